// round 5
// baseline (speedup 1.0000x reference)
#include <cuda_runtime.h>

// InputEmbedding: out[b,t,v,d] = features[b,t,v] * W[v,d] + b[v,d] + pos[b,t,d]
// pos = concat( tod_table[bar_in_day[b,t]] (128),
//               dow_table[day_of_week[b]]  (32),
//               dom_table[day_of_month[b]] (32),
//               doy_table[day_of_year[b]]  (64) )
//
// Shapes: B=64, T=288, V=24, D=256. Output fp32, 453 MB -> store-BW bound.

#define Bsz 64
#define Tlen 288
#define Vn 24
#define Dn 256
#define D4n 64            // D / 4

__global__ __launch_bounds__(256)
void input_embedding_kernel(
    const float*  __restrict__ features,     // (B,T,V)
    const int*    __restrict__ bar_in_day,   // (B,T)
    const int*    __restrict__ day_of_week,  // (B,)
    const int*    __restrict__ day_of_month, // (B,)
    const int*    __restrict__ day_of_year,  // (B,)
    const float4* __restrict__ W4,           // (V, D/4)
    const float4* __restrict__ b4,           // (V, D/4)
    const float4* __restrict__ tod4,         // (288, 32)
    const float4* __restrict__ dow4,         // (7, 8)
    const float4* __restrict__ dom4,         // (32, 8)
    const float4* __restrict__ doy4,         // (367, 16)
    float4*       __restrict__ out,          // (B,T,V,D/4)
    int n4)
{
    int idx = blockIdx.x * blockDim.x + threadIdx.x;
    if (idx >= n4) return;

    int d4 = idx & (D4n - 1);       // 0..63
    int rv = idx >> 6;              // (b*T + t)*V + v   == flat index into features
    int v  = rv % Vn;
    int bt = rv / Vn;               // b*T + t
    int b  = bt / Tlen;

    float  x  = __ldg(&features[rv]);
    float4 w  = __ldg(&W4[v * D4n + d4]);
    float4 bi = __ldg(&b4[v * D4n + d4]);

    // positional float4 for this d-chunk
    float4 p;
    if (d4 < 32) {                                   // d in [0,128): time-of-day
        int bid = __ldg(&bar_in_day[bt]);
        p = __ldg(&tod4[bid * 32 + d4]);
    } else if (d4 < 40) {                            // d in [128,160): day-of-week
        p = __ldg(&dow4[__ldg(&day_of_week[b]) * 8 + (d4 - 32)]);
    } else if (d4 < 48) {                            // d in [160,192): day-of-month
        p = __ldg(&dom4[__ldg(&day_of_month[b]) * 8 + (d4 - 40)]);
    } else {                                         // d in [192,256): day-of-year
        p = __ldg(&doy4[__ldg(&day_of_year[b]) * 16 + (d4 - 48)]);
    }

    float4 o;
    o.x = fmaf(x, w.x, bi.x) + p.x;
    o.y = fmaf(x, w.y, bi.y) + p.y;
    o.z = fmaf(x, w.z, bi.z) + p.z;
    o.w = fmaf(x, w.w, bi.w) + p.w;

    // streaming store: output is never re-read, keep L2 for the table gathers
    __stcs(&out[idx], o);
}

extern "C" void kernel_launch(void* const* d_in, const int* in_sizes, int n_in,
                              void* d_out, int out_size)
{
    const float* features     = (const float*)d_in[0];
    const int*   bar_in_day   = (const int*)  d_in[1];
    const int*   day_of_week  = (const int*)  d_in[2];
    const int*   day_of_month = (const int*)  d_in[3];
    const int*   day_of_year  = (const int*)  d_in[4];
    const float* W            = (const float*)d_in[5];
    const float* bvec         = (const float*)d_in[6];
    const float* tod          = (const float*)d_in[7];
    const float* dow          = (const float*)d_in[8];
    const float* dom          = (const float*)d_in[9];
    const float* doy          = (const float*)d_in[10];

    int n4 = out_size / 4;                 // 28,311,552 float4s
    int threads = 256;
    int blocks = (n4 + threads - 1) / threads;

    input_embedding_kernel<<<blocks, threads>>>(
        features, bar_in_day, day_of_week, day_of_month, day_of_year,
        (const float4*)W, (const float4*)bvec,
        (const float4*)tod, (const float4*)dow,
        (const float4*)dom, (const float4*)doy,
        (float4*)d_out, n4);
}

// round 6
// speedup vs baseline: 1.2342x; 1.2342x over previous
#include <cuda_runtime.h>

// InputEmbedding: out[b,t,v,d] = features[b,t,v] * W[v,d] + b[v,d] + pos[b,t,d]
// pos = concat( tod_table[bar_in_day[b,t]] (d 0..127),
//               dow_table[day_of_week[b]]  (d 128..159),
//               dom_table[day_of_month[b]] (d 160..191),
//               doy_table[day_of_year[b]]  (d 192..255) )
//
// B=64, T=288, V=24, D=256. Output 453 MB fp32 -> goal: DRAM-store bound.
//
// Layout: thread owns fixed (v, d4); W/b live in registers; loop over a
// T-chunk with fixed batch b. Warps with d4<32 gather tod per t; warps with
// d4>=32 have a loop-invariant pos (depends only on b) hoisted to registers.

#define Tlen  288
#define Vn    24
#define D4n   64            // D/4 float4s per row
#define TCH   32            // t's per block
#define VG    4             // v's per block (tid>>6)

__global__ __launch_bounds__(256)
void input_embedding_kernel(
    const float*  __restrict__ features,     // (B,T,V)
    const int*    __restrict__ bar_in_day,   // (B,T)
    const int*    __restrict__ day_of_week,  // (B,)
    const int*    __restrict__ day_of_month, // (B,)
    const int*    __restrict__ day_of_year,  // (B,)
    const float4* __restrict__ W4,           // (V, 64)
    const float4* __restrict__ b4,           // (V, 64)
    const float4* __restrict__ tod4,         // (288, 32)
    const float4* __restrict__ dow4,         // (7, 8)
    const float4* __restrict__ dom4,         // (32, 8)
    const float4* __restrict__ doy4,         // (367, 16)
    float4*       __restrict__ out)          // (B,T,V,64)
{
    const int tid = threadIdx.x;
    const int d4  = tid & (D4n - 1);   // 0..63
    const int vg  = tid >> 6;          // 0..3
    const int b   = blockIdx.x;        // 0..63
    const int tc  = blockIdx.y;        // 0..8
    const int v   = blockIdx.z * VG + vg;  // 0..23

    // loop-invariant per-thread state
    const float4 w  = __ldg(&W4[v * D4n + d4]);
    const float4 bi = __ldg(&b4[v * D4n + d4]);

    const bool tod_lane = (d4 < 32);   // uniform per warp
    float4 pc = make_float4(0.f, 0.f, 0.f, 0.f);
    if (!tod_lane) {
        if (d4 < 40)      pc = __ldg(&dow4[__ldg(&day_of_week[b])  * 8  + (d4 - 32)]);
        else if (d4 < 48) pc = __ldg(&dom4[__ldg(&day_of_month[b]) * 8  + (d4 - 40)]);
        else              pc = __ldg(&doy4[__ldg(&day_of_year[b])  * 16 + (d4 - 48)]);
    }

    const int bt0 = b * Tlen + tc * TCH;
    const float* fptr = features + bt0 * Vn + v;
    const int*   bidp = bar_in_day + bt0;
    float4*      optr = out + (bt0 * Vn + v) * D4n + d4;

    #pragma unroll 4
    for (int i = 0; i < TCH; i++) {
        const float x = __ldg(fptr + i * Vn);

        float4 p = pc;
        if (tod_lane) {
            const int bid = __ldg(bidp + i);
            p = __ldg(&tod4[bid * 32 + d4]);
        }

        float4 o;
        o.x = fmaf(x, w.x, bi.x) + p.x;
        o.y = fmaf(x, w.y, bi.y) + p.y;
        o.z = fmaf(x, w.z, bi.z) + p.z;
        o.w = fmaf(x, w.w, bi.w) + p.w;

        __stcs(optr + i * (Vn * D4n), o);   // streaming: never re-read
    }
}

extern "C" void kernel_launch(void* const* d_in, const int* in_sizes, int n_in,
                              void* d_out, int out_size)
{
    const float* features     = (const float*)d_in[0];
    const int*   bar_in_day   = (const int*)  d_in[1];
    const int*   day_of_week  = (const int*)  d_in[2];
    const int*   day_of_month = (const int*)  d_in[3];
    const int*   day_of_year  = (const int*)  d_in[4];
    const float* W            = (const float*)d_in[5];
    const float* bvec         = (const float*)d_in[6];
    const float* tod          = (const float*)d_in[7];
    const float* dow          = (const float*)d_in[8];
    const float* dom          = (const float*)d_in[9];
    const float* doy          = (const float*)d_in[10];

    dim3 grid(64, Tlen / TCH, Vn / VG);   // (64, 9, 6) = 3456 blocks
    input_embedding_kernel<<<grid, 256>>>(
        features, bar_in_day, day_of_week, day_of_month, day_of_year,
        (const float4*)W, (const float4*)bvec,
        (const float4*)tod, (const float4*)dow,
        (const float4*)dom, (const float4*)doy,
        (float4*)d_out);
}